// round 10
// baseline (speedup 1.0000x reference)
#include <cuda_runtime.h>
#include <cuda_fp16.h>
#include <cstdint>
#include <math.h>

#define N_NODES 50000
#define N_EDGES 1600000
#define DIM     128
#define RC      5.0f
#define DEPTH   3

#define SCAN_BLK 1024
#define N_CHUNKS ((N_NODES + SCAN_BLK - 1) / SCAN_BLK)   // 49

typedef unsigned long long u64;

// ---------------- persistent device scratch (no allocation APIs) -------------
__device__ int    g_counts[N_NODES];
__device__ int    g_rowptr[N_NODES + 1];
__device__ int    g_bsum[N_CHUNKS];
__device__ int    g_slot[N_EDGES];              // per-edge slot within its dst list
__device__ int2   g_csr[N_EDGES];               // (src, f bits) packed, one 8B load/edge
__device__ __half g_curh[N_NODES * DIM];        // fp16 copy of current features (gather source)
__device__ float  g_x[N_NODES * DIM];           // x = segment_sum + v  (GEMM input, fp32)

// ---------------- f32x2 packed-FMA helpers (exact fp32, 2 FMA/instr) ---------
__device__ __forceinline__ u64 pk2(float lo, float hi) {
    u64 r; asm("mov.b64 %0, {%1, %2};" : "=l"(r) : "f"(lo), "f"(hi)); return r;
}
__device__ __forceinline__ void ffma2(u64& d, u64 a, u64 b) {
    asm("fma.rn.f32x2 %0, %1, %2, %0;" : "+l"(d) : "l"(a), "l"(b));
}
__device__ __forceinline__ void unpk2(u64 v, float& lo, float& hi) {
    asm("mov.b64 {%0, %1}, %2;" : "=f"(lo), "=f"(hi) : "l"(v));
}

// ---------------------------------------------------------------------------
// init: zero histogram + build fp16 copy of v (layer-0 gather source)
__global__ void k_init(const float* __restrict__ v)
{
    int i = blockIdx.x * blockDim.x + threadIdx.x;
    if (i < N_NODES) g_counts[i] = 0;
    if (i == 0) g_rowptr[0] = 0;
    if (i < N_NODES * 32) {
        float4 f = reinterpret_cast<const float4*>(v)[i];
        __half2 h0 = __floats2half2_rn(f.x, f.y);
        __half2 h1 = __floats2half2_rn(f.z, f.w);
        uint2 raw;
        raw.x = *reinterpret_cast<unsigned*>(&h0);
        raw.y = *reinterpret_cast<unsigned*>(&h1);
        reinterpret_cast<uint2*>(g_curh)[i] = raw;
    }
}

// histogram + slot assignment in one atomic pass
__global__ void k_hist(const int* __restrict__ dst)
{
    int e = blockIdx.x * blockDim.x + threadIdx.x;
    if (e < N_EDGES) g_slot[e] = atomicAdd(&g_counts[dst[e]], 1);
}

// per-chunk inclusive scan
__global__ void k_scan1()
{
    __shared__ int s[SCAN_BLK];
    int t = threadIdx.x;
    int i = blockIdx.x * SCAN_BLK + t;
    s[t] = (i < N_NODES) ? g_counts[i] : 0;
    __syncthreads();
    for (int off = 1; off < SCAN_BLK; off <<= 1) {
        int add = (t >= off) ? s[t - off] : 0;
        __syncthreads();
        s[t] += add;
        __syncthreads();
    }
    if (i < N_NODES) g_rowptr[i + 1] = s[t];
    if (t == SCAN_BLK - 1) g_bsum[blockIdx.x] = s[t];
}

// add prefix of chunk sums; chunk offset via tree reduce
__global__ void k_scan3()
{
    __shared__ int sb[64];
    int t = threadIdx.x;
    if (t < 64) sb[t] = (t < (int)blockIdx.x && t < N_CHUNKS) ? g_bsum[t] : 0;
    __syncthreads();
    for (int o = 32; o > 0; o >>= 1) {
        if (t < o) sb[t] += sb[t + o];
        __syncthreads();
    }
    int off = sb[0];
    int i = blockIdx.x * SCAN_BLK + t;
    if (i < N_NODES) g_rowptr[i + 1] += off;
}

// scatter edges into CSR order (atomic-free); fold the edge envelope in here
__global__ void k_fill(const int* __restrict__ src, const int* __restrict__ dst,
                       const float* __restrict__ e_in,
                       const float* __restrict__ rs, const float* __restrict__ sigma)
{
    int e = blockIdx.x * blockDim.x + threadIdx.x;
    if (e >= N_EDGES) return;
    int n = dst[e];
    int p = g_rowptr[n] + g_slot[e];

    float r   = e_in[e];
    float d   = r - rs[0];
    float sg  = sigma[0];
    float gau = expf(-(d * d) / (sg * sg));
    float cut = (r < RC) ? 0.5f * cosf(0.62831853071795864769f * r) : 0.0f; // pi/RC
    g_csr[p] = make_int2(src[e], __float_as_int(gau * cut));
}

// one warp per node: x[n] = v[n] + sum_{edges->n} f * curh[src]
// Meta for 32 edges staged via one coalesced int2 load -> deep gather MLP.
__global__ void __launch_bounds__(256)
k_aggregate(const float* __restrict__ v)
{
    __shared__ int2 s_meta[8][32];
    int gtid = blockIdx.x * blockDim.x + threadIdx.x;
    int node = gtid >> 5;
    int lane = gtid & 31;
    int w    = threadIdx.x >> 5;
    if (node >= N_NODES) return;

    int p0 = __ldg(&g_rowptr[node]);
    int p1 = __ldg(&g_rowptr[node + 1]);

    const uint2* in = reinterpret_cast<const uint2*>(g_curh);
    float4 acc = make_float4(0.f, 0.f, 0.f, 0.f);

    for (int base = p0; base < p1; base += 32) {
        int idx = base + lane;
        if (idx < p1) s_meta[w][lane] = __ldg(&g_csr[idx]);
        __syncwarp();
        int cnt = min(32, p1 - base);
#pragma unroll 8
        for (int j = 0; j < cnt; j++) {
            int2 m = s_meta[w][j];
            float f = __int_as_float(m.y);
            uint2 r = __ldg(&in[(size_t)m.x * 32 + lane]);
            float2 a = __half22float2(*reinterpret_cast<__half2*>(&r.x));
            float2 b = __half22float2(*reinterpret_cast<__half2*>(&r.y));
            acc.x += f * a.x; acc.y += f * a.y; acc.z += f * b.x; acc.w += f * b.y;
        }
        __syncwarp();
    }

    float4 vv = *reinterpret_cast<const float4*>(v + (size_t)node * DIM + lane * 4);
    acc.x += vv.x; acc.y += vv.y; acc.z += vv.z; acc.w += vv.w;
    *reinterpret_cast<float4*>(g_x + (size_t)node * DIM + lane * 4) = acc;
}

// out = relu(x @ A^T + b) via packed f32x2 FMAs (exact fp32).
// Block: 128 threads, tile 64 rows x 128 cols; thread = 8 rows x 8 cols.
#define LIN_ROWS  64
#define XS_STRIDE 130   // pad: row-strided LDS.64 hits distinct bank pairs
__global__ void __launch_bounds__(128, 2)
k_linear(const float* __restrict__ A, const float* __restrict__ b,
         float* __restrict__ dout, int last)
{
    extern __shared__ float smem[];
    float* As = smem;                       // [k][c]  128*128
    float* xs = smem + DIM * DIM;           // [r][k]  stride XS_STRIDE, 64 rows

    int tid = threadIdx.x;
    int cg  = tid & 15;
    int rg  = tid >> 4;

    // As[k*128 + c] = A[c*128 + k]   (A_w is [out_c][in_k], we need k-major)
    for (int idx = tid; idx < DIM * DIM; idx += 128) {
        int k = idx >> 7, c = idx & 127;
        As[idx] = A[c * DIM + k];
    }
    int row0 = blockIdx.x * LIN_ROWS;
    for (int idx = tid; idx < LIN_ROWS * DIM; idx += 128) {
        int r = idx >> 7, k = idx & 127;
        xs[r * XS_STRIDE + k] =
            (row0 + r < N_NODES) ? g_x[(size_t)(row0 + r) * DIM + k] : 0.f;
    }
    __syncthreads();

    u64 acc[8][4];
#pragma unroll
    for (int r = 0; r < 8; r++)
#pragma unroll
        for (int j = 0; j < 4; j++) acc[r][j] = 0ull;

    const float* xrow = xs + rg * 8 * XS_STRIDE;
    const float* acol = As + cg * 8;

#pragma unroll 2
    for (int k = 0; k < DIM; k += 2) {
        // A pairs for k and k+1: 8 cols = 4 f32x2 each, loaded directly as u64 pairs
        ulonglong2 a00 = *reinterpret_cast<const ulonglong2*>(acol + k * DIM);
        ulonglong2 a01 = *reinterpret_cast<const ulonglong2*>(acol + k * DIM + 4);
        ulonglong2 a10 = *reinterpret_cast<const ulonglong2*>(acol + (k + 1) * DIM);
        ulonglong2 a11 = *reinterpret_cast<const ulonglong2*>(acol + (k + 1) * DIM + 4);
        u64 ak0[4] = { a00.x, a00.y, a01.x, a01.y };
        u64 ak1[4] = { a10.x, a10.y, a11.x, a11.y };
#pragma unroll
        for (int r = 0; r < 8; r++) {
            float2 xv = *reinterpret_cast<const float2*>(xrow + r * XS_STRIDE + k);
            u64 dx0 = pk2(xv.x, xv.x);
            u64 dx1 = pk2(xv.y, xv.y);
#pragma unroll
            for (int j = 0; j < 4; j++) {
                ffma2(acc[r][j], ak0[j], dx0);
                ffma2(acc[r][j], ak1[j], dx1);
            }
        }
    }

    float4 b0 = *reinterpret_cast<const float4*>(b + cg * 8);
    float4 b1 = *reinterpret_cast<const float4*>(b + cg * 8 + 4);

#pragma unroll
    for (int r = 0; r < 8; r++) {
        int row = row0 + rg * 8 + r;
        if (row >= N_NODES) break;
        float o[8];
        unpk2(acc[r][0], o[0], o[1]);
        unpk2(acc[r][1], o[2], o[3]);
        unpk2(acc[r][2], o[4], o[5]);
        unpk2(acc[r][3], o[6], o[7]);
        o[0] = fmaxf(o[0] + b0.x, 0.f); o[1] = fmaxf(o[1] + b0.y, 0.f);
        o[2] = fmaxf(o[2] + b0.z, 0.f); o[3] = fmaxf(o[3] + b0.w, 0.f);
        o[4] = fmaxf(o[4] + b1.x, 0.f); o[5] = fmaxf(o[5] + b1.y, 0.f);
        o[6] = fmaxf(o[6] + b1.z, 0.f); o[7] = fmaxf(o[7] + b1.w, 0.f);
        if (last) {
            float4* dst0 = reinterpret_cast<float4*>(dout + (size_t)row * DIM + cg * 8);
            dst0[0] = make_float4(o[0], o[1], o[2], o[3]);
            dst0[1] = make_float4(o[4], o[5], o[6], o[7]);
        } else {
            __half2 h0 = __floats2half2_rn(o[0], o[1]);
            __half2 h1 = __floats2half2_rn(o[2], o[3]);
            __half2 h2 = __floats2half2_rn(o[4], o[5]);
            __half2 h3 = __floats2half2_rn(o[6], o[7]);
            uint2 raw0, raw1;
            raw0.x = *reinterpret_cast<unsigned*>(&h0);
            raw0.y = *reinterpret_cast<unsigned*>(&h1);
            raw1.x = *reinterpret_cast<unsigned*>(&h2);
            raw1.y = *reinterpret_cast<unsigned*>(&h3);
            uint2* hq = reinterpret_cast<uint2*>(g_curh) + (size_t)row * 32 + cg * 2;
            hq[0] = raw0;
            hq[1] = raw1;
        }
    }
}

// ---------------------------------------------------------------------------
extern "C" void kernel_launch(void* const* d_in, const int* in_sizes, int n_in,
                              void* d_out, int out_size)
{
    const float* v     = (const float*)d_in[0];
    const float* e     = (const float*)d_in[1];
    const int*   src   = (const int*)d_in[2];
    const int*   dst   = (const int*)d_in[3];
    const float* A_w   = (const float*)d_in[4];
    const float* A_b   = (const float*)d_in[5];
    const float* rs    = (const float*)d_in[6];
    const float* sigma = (const float*)d_in[7];
    float* out = (float*)d_out;

    (void)in_sizes; (void)n_in; (void)out_size;

    const int SMEM_LIN = (DIM * DIM + LIN_ROWS * XS_STRIDE) * (int)sizeof(float); // ~98KB
    (void)cudaFuncSetAttribute(k_linear, cudaFuncAttributeMaxDynamicSharedMemorySize, SMEM_LIN);

    int gE = (N_EDGES + 255) / 256;

    // build CSR (per launch; inputs are constant so this is deterministic work)
    k_init <<<(N_NODES * 32 + 255) / 256, 256>>>(v);
    k_hist <<<gE, 256>>>(dst);
    k_scan1<<<N_CHUNKS, SCAN_BLK>>>();
    k_scan3<<<N_CHUNKS, SCAN_BLK>>>();
    k_fill <<<gE, 256>>>(src, dst, e, rs, sigma);

    int aggBlocks = (N_NODES * 32 + 255) / 256;           // warp per node
    int linBlocks = (N_NODES + LIN_ROWS - 1) / LIN_ROWS;  // 782

    for (int d = 0; d < DEPTH; d++) {
        k_aggregate<<<aggBlocks, 256>>>(v);
        k_linear<<<linBlocks, 128, SMEM_LIN>>>(A_w, A_b, out, d == DEPTH - 1 ? 1 : 0);
    }
}

// round 12
// speedup vs baseline: 1.9561x; 1.9561x over previous
#include <cuda_runtime.h>
#include <cuda_fp16.h>
#include <cstdint>
#include <math.h>

#define N_NODES 50000
#define N_EDGES 1600000
#define DIM     128
#define RC      5.0f
#define DEPTH   3

#define SCAN_BLK 1024
#define N_CHUNKS ((N_NODES + SCAN_BLK - 1) / SCAN_BLK)   // 49

// ---------------- persistent device scratch (no allocation APIs) -------------
__device__ int    g_counts[N_NODES];
__device__ int    g_rowloc[N_NODES + 1];        // chunk-local inclusive scan
__device__ int    g_rowptr[N_NODES + 1];        // finalized CSR row pointers
__device__ int    g_bsum[N_CHUNKS];             // per-chunk totals
__device__ int    g_slot[N_EDGES];              // per-edge slot within its dst list
__device__ int2   g_csr[N_EDGES];               // (src, f bits) packed
__device__ __half g_curh[N_NODES * DIM];        // fp16 current features (gather source)
__device__ __half g_xh[N_NODES * DIM];          // fp16 x = segment_sum + v (GEMM input)

// ---------------------------------------------------------------------------
// histogram + slot assignment + fp16 copy of v (N_NODES*32 == N_EDGES == 1.6M)
__global__ void k_hist(const int* __restrict__ dst, const float* __restrict__ v)
{
    int e = blockIdx.x * blockDim.x + threadIdx.x;
    if (e >= N_EDGES) return;
    g_slot[e] = atomicAdd(&g_counts[dst[e]], 1);
    // v -> fp16 (e indexes float4 quads; N_NODES*32 quads == N_EDGES threads)
    float4 f = reinterpret_cast<const float4*>(v)[e];
    __half2 h0 = __floats2half2_rn(f.x, f.y);
    __half2 h1 = __floats2half2_rn(f.z, f.w);
    uint2 raw;
    raw.x = *reinterpret_cast<unsigned*>(&h0);
    raw.y = *reinterpret_cast<unsigned*>(&h1);
    reinterpret_cast<uint2*>(g_curh)[e] = raw;
}

// per-chunk inclusive scan (chunk-local only; no cross-chunk dependency)
__global__ void __launch_bounds__(SCAN_BLK)
k_scan1()
{
    __shared__ int s[SCAN_BLK];
    int t = threadIdx.x;
    int i = blockIdx.x * SCAN_BLK + t;
    s[t] = (i < N_NODES) ? g_counts[i] : 0;
    __syncthreads();
    for (int off = 1; off < SCAN_BLK; off <<= 1) {
        int add = (t >= off) ? s[t - off] : 0;
        __syncthreads();
        s[t] += add;
        __syncthreads();
    }
    if (i < N_NODES) g_rowloc[i + 1] = s[t];
    if (t == SCAN_BLK - 1) g_bsum[blockIdx.x] = s[t];
    if (i == 0) { g_rowloc[0] = 0; g_rowptr[0] = 0; }
}

// CSR fill + rowptr finalize. Each block rebuilds the 49-entry chunk-offset
// LUT in shared memory (cheap) -- no grid sync anywhere.
__global__ void __launch_bounds__(256)
k_fill(const int* __restrict__ src, const int* __restrict__ dst,
       const float* __restrict__ e_in,
       const float* __restrict__ rs, const float* __restrict__ sigma)
{
    __shared__ int lut[N_CHUNKS];                 // exclusive prefix of chunk sums
    if (threadIdx.x == 0) {
        int run = 0;
        for (int c = 0; c < N_CHUNKS; c++) { lut[c] = run; run += g_bsum[c]; }
    }
    __syncthreads();

    int stride = gridDim.x * blockDim.x;
    int t0 = blockIdx.x * blockDim.x + threadIdx.x;

    // finalize rowptr for the aggregate kernel
    for (int i = t0; i < N_NODES; i += stride)
        g_rowptr[i + 1] = g_rowloc[i + 1] + lut[i >> 10];

    // scatter edges into CSR order, folding in the edge envelope
    float rsv = rs[0], sg = sigma[0];
    for (int e = t0; e < N_EDGES; e += stride) {
        int n = dst[e];
        int base = (n == 0) ? 0 : (g_rowloc[n] + lut[(n - 1) >> 10]);
        int p = base + g_slot[e];
        float r   = e_in[e];
        float d   = r - rsv;
        float gau = expf(-(d * d) / (sg * sg));
        float cut = (r < RC) ? 0.5f * cosf(0.62831853071795864769f * r) : 0.0f; // pi/RC
        g_csr[p] = make_int2(src[e], __float_as_int(gau * cut));
    }
}

// one warp per node: xh[n] = fp16( v[n] + sum_{edges->n} f * curh[src] )
__global__ void __launch_bounds__(256)
k_aggregate(const float* __restrict__ v)
{
    __shared__ int2 s_meta[8][32];
    int gtid = blockIdx.x * blockDim.x + threadIdx.x;
    int node = gtid >> 5;
    int lane = gtid & 31;
    int w    = threadIdx.x >> 5;
    if (node >= N_NODES) return;

    int p0 = __ldg(&g_rowptr[node]);
    int p1 = __ldg(&g_rowptr[node + 1]);

    const uint2* in = reinterpret_cast<const uint2*>(g_curh);
    float4 acc = make_float4(0.f, 0.f, 0.f, 0.f);

    for (int base = p0; base < p1; base += 32) {
        int idx = base + lane;
        if (idx < p1) s_meta[w][lane] = __ldg(&g_csr[idx]);
        __syncwarp();
        int cnt = min(32, p1 - base);
#pragma unroll 8
        for (int j = 0; j < cnt; j++) {
            int2 m = s_meta[w][j];
            float f = __int_as_float(m.y);
            uint2 r = __ldg(&in[(size_t)m.x * 32 + lane]);
            float2 a = __half22float2(*reinterpret_cast<__half2*>(&r.x));
            float2 b = __half22float2(*reinterpret_cast<__half2*>(&r.y));
            acc.x += f * a.x; acc.y += f * a.y; acc.z += f * b.x; acc.w += f * b.y;
        }
        __syncwarp();
    }

    float4 vv = *reinterpret_cast<const float4*>(v + (size_t)node * DIM + lane * 4);
    acc.x += vv.x; acc.y += vv.y; acc.z += vv.z; acc.w += vv.w;
    __half2 h0 = __floats2half2_rn(acc.x, acc.y);
    __half2 h1 = __floats2half2_rn(acc.z, acc.w);
    uint2 raw;
    raw.x = *reinterpret_cast<unsigned*>(&h0);
    raw.y = *reinterpret_cast<unsigned*>(&h1);
    reinterpret_cast<uint2*>(g_xh)[(size_t)node * 32 + lane] = raw;
}

// out = relu(x @ A^T + b) on tensor cores: mma.sync m16n8k16 f16 -> f32.
// Block 256 thr = 8 warps; tile 64 rows x 128 cols; warp = 16 rows x 64 cols.
#define LIN_ROWS 64
#define PADK     136   // smem stride in halfs: word stride 68 -> conflict-free frags
__global__ void __launch_bounds__(256)
k_linear(const float* __restrict__ A, const float* __restrict__ b,
         float* __restrict__ dout, int last)
{
    extern __shared__ __half smem[];
    __half* As = smem;                       // [c][k] stride PADK  (B operand)
    __half* xs = smem + DIM * PADK;          // [m][k] stride PADK  (A operand)

    int tid  = threadIdx.x;
    int wid  = tid >> 5;
    int lane = tid & 31;
    int g    = lane >> 2;                    // 0..7
    int tg   = lane & 3;                     // 0..3
    int wm   = wid & 3;                      // m-quadrant (16 rows)
    int wn   = wid >> 2;                     // n-half (64 cols)

    // As[c][k] = fp16(A[c*128 + k])  (A_w native layout; no transpose needed)
    for (int idx = tid; idx < DIM * DIM; idx += 256) {
        int c = idx >> 7, k = idx & 127;
        As[c * PADK + k] = __float2half_rn(A[idx]);
    }
    // xs rows (zero-pad past N_NODES)
    int row0 = blockIdx.x * LIN_ROWS;
    unsigned* xs32 = reinterpret_cast<unsigned*>(xs);
    const unsigned* xh32 = reinterpret_cast<const unsigned*>(g_xh);
    for (int idx = tid; idx < LIN_ROWS * 64; idx += 256) {   // u32 units (2 halfs)
        int r = idx >> 6, kk = idx & 63;
        unsigned val = (row0 + r < N_NODES) ? xh32[(size_t)(row0 + r) * 64 + kk] : 0u;
        xs32[r * (PADK / 2) + kk] = val;
    }
    __syncthreads();

    float d[8][4];
#pragma unroll
    for (int nt = 0; nt < 8; nt++)
#pragma unroll
        for (int j = 0; j < 4; j++) d[nt][j] = 0.f;

    const unsigned* xsu = reinterpret_cast<const unsigned*>(xs);
    const unsigned* asu = reinterpret_cast<const unsigned*>(As);
    int m0 = wm * 16;
    int n0 = wn * 64;

#pragma unroll
    for (int kt = 0; kt < 8; kt++) {
        int k0 = kt * 16;
        // A fragment (x tile): rows {m0+g, m0+g+8}, k pairs {2tg, 2tg+8}
        unsigned a0 = xsu[(m0 + g)     * 68 + (k0 >> 1) + tg];
        unsigned a1 = xsu[(m0 + g + 8) * 68 + (k0 >> 1) + tg];
        unsigned a2 = xsu[(m0 + g)     * 68 + (k0 >> 1) + tg + 4];
        unsigned a3 = xsu[(m0 + g + 8) * 68 + (k0 >> 1) + tg + 4];
#pragma unroll
        for (int nt = 0; nt < 8; nt++) {
            int n = n0 + nt * 8 + g;
            unsigned b0 = asu[n * 68 + (k0 >> 1) + tg];
            unsigned b1 = asu[n * 68 + (k0 >> 1) + tg + 4];
            asm volatile(
                "mma.sync.aligned.m16n8k16.row.col.f32.f16.f16.f32 "
                "{%0,%1,%2,%3}, {%4,%5,%6,%7}, {%8,%9}, {%0,%1,%2,%3};"
                : "+f"(d[nt][0]), "+f"(d[nt][1]), "+f"(d[nt][2]), "+f"(d[nt][3])
                : "r"(a0), "r"(a1), "r"(a2), "r"(a3), "r"(b0), "r"(b1));
        }
    }

    // epilogue: bias + relu; thread owns cols {n0+nt*8+2tg,+1}, rows {m0+g, m0+g+8}
#pragma unroll
    for (int nt = 0; nt < 8; nt++) {
        int col = n0 + nt * 8 + tg * 2;
        float2 bb = *reinterpret_cast<const float2*>(b + col);
        float o0 = fmaxf(d[nt][0] + bb.x, 0.f);
        float o1 = fmaxf(d[nt][1] + bb.y, 0.f);
        float o2 = fmaxf(d[nt][2] + bb.x, 0.f);
        float o3 = fmaxf(d[nt][3] + bb.y, 0.f);
        int r0 = row0 + m0 + g;
        int r1 = r0 + 8;
        if (last) {
            if (r0 < N_NODES)
                *reinterpret_cast<float2*>(dout + (size_t)r0 * DIM + col) = make_float2(o0, o1);
            if (r1 < N_NODES)
                *reinterpret_cast<float2*>(dout + (size_t)r1 * DIM + col) = make_float2(o2, o3);
        } else {
            unsigned* ch = reinterpret_cast<unsigned*>(g_curh);
            if (r0 < N_NODES) {
                __half2 h = __floats2half2_rn(o0, o1);
                ch[(size_t)r0 * 64 + (col >> 1)] = *reinterpret_cast<unsigned*>(&h);
            }
            if (r1 < N_NODES) {
                __half2 h = __floats2half2_rn(o2, o3);
                ch[(size_t)r1 * 64 + (col >> 1)] = *reinterpret_cast<unsigned*>(&h);
            }
        }
    }
}

// ---------------------------------------------------------------------------
extern "C" void kernel_launch(void* const* d_in, const int* in_sizes, int n_in,
                              void* d_out, int out_size)
{
    const float* v     = (const float*)d_in[0];
    const float* e     = (const float*)d_in[1];
    const int*   src   = (const int*)d_in[2];
    const int*   dst   = (const int*)d_in[3];
    const float* A_w   = (const float*)d_in[4];
    const float* A_b   = (const float*)d_in[5];
    const float* rs    = (const float*)d_in[6];
    const float* sigma = (const float*)d_in[7];
    float* out = (float*)d_out;

    (void)in_sizes; (void)n_in; (void)out_size;

    const int SMEM_LIN = (DIM + LIN_ROWS) * PADK * (int)sizeof(__half); // ~51KB
    (void)cudaFuncSetAttribute(k_linear, cudaFuncAttributeMaxDynamicSharedMemorySize, SMEM_LIN);

    // zero the histogram with a memset node (graph-capturable, not an alloc)
    void* counts_ptr = nullptr;
    (void)cudaGetSymbolAddress(&counts_ptr, g_counts);
    (void)cudaMemsetAsync(counts_ptr, 0, N_NODES * sizeof(int));

    int gE = (N_EDGES + 255) / 256;

    k_hist <<<gE, 256>>>(dst, v);
    k_scan1<<<N_CHUNKS, SCAN_BLK>>>();
    k_fill <<<2048, 256>>>(src, dst, e, rs, sigma);

    int aggBlocks = (N_NODES * 32 + 255) / 256;           // warp per node
    int linBlocks = (N_NODES + LIN_ROWS - 1) / LIN_ROWS;  // 782

    for (int d = 0; d < DEPTH; d++) {
        k_aggregate<<<aggBlocks, 256>>>(v);
        k_linear<<<linBlocks, 256, SMEM_LIN>>>(A_w, A_b, out, d == DEPTH - 1 ? 1 : 0);
    }
}

// round 13
// speedup vs baseline: 2.0410x; 1.0434x over previous
#include <cuda_runtime.h>
#include <cuda_fp16.h>
#include <cstdint>
#include <math.h>

#define N_NODES 50000
#define N_EDGES 1600000
#define DIM     128
#define RC      5.0f
#define DEPTH   3

#define SCAN_BLK 1024
#define N_CHUNKS ((N_NODES + SCAN_BLK - 1) / SCAN_BLK)   // 49

// ---------------- persistent device scratch (no allocation APIs) -------------
__device__ int    g_counts[N_NODES];
__device__ int    g_rowloc[N_NODES + 1];        // chunk-local inclusive scan
__device__ int    g_rowptr[N_NODES + 1];        // finalized CSR row pointers
__device__ int    g_bsum[N_CHUNKS];             // per-chunk totals
__device__ int    g_slot[N_EDGES];              // per-edge slot within its dst list
__device__ int2   g_csr[N_EDGES];               // (src, f as duplicated half2)
__device__ __half g_curh[N_NODES * DIM];        // fp16 current features (gather source)
__device__ __half g_xh[N_NODES * DIM];          // fp16 x = segment_sum + v (GEMM input)

// ---------------------------------------------------------------------------
// histogram + slot assignment + fp16 copy of v (N_NODES*32 == N_EDGES == 1.6M)
__global__ void k_hist(const int* __restrict__ dst, const float* __restrict__ v)
{
    int e = blockIdx.x * blockDim.x + threadIdx.x;
    if (e >= N_EDGES) return;
    g_slot[e] = atomicAdd(&g_counts[dst[e]], 1);
    // v -> fp16 (e indexes float4 quads; N_NODES*32 quads == N_EDGES threads)
    float4 f = reinterpret_cast<const float4*>(v)[e];
    __half2 h0 = __floats2half2_rn(f.x, f.y);
    __half2 h1 = __floats2half2_rn(f.z, f.w);
    uint2 raw;
    raw.x = *reinterpret_cast<unsigned*>(&h0);
    raw.y = *reinterpret_cast<unsigned*>(&h1);
    reinterpret_cast<uint2*>(g_curh)[e] = raw;
}

// per-chunk inclusive scan (chunk-local only; no cross-chunk dependency)
__global__ void __launch_bounds__(SCAN_BLK)
k_scan1()
{
    __shared__ int s[SCAN_BLK];
    int t = threadIdx.x;
    int i = blockIdx.x * SCAN_BLK + t;
    s[t] = (i < N_NODES) ? g_counts[i] : 0;
    __syncthreads();
    for (int off = 1; off < SCAN_BLK; off <<= 1) {
        int add = (t >= off) ? s[t - off] : 0;
        __syncthreads();
        s[t] += add;
        __syncthreads();
    }
    if (i < N_NODES) g_rowloc[i + 1] = s[t];
    if (t == SCAN_BLK - 1) g_bsum[blockIdx.x] = s[t];
    if (i == 0) { g_rowloc[0] = 0; g_rowptr[0] = 0; }
}

// CSR fill + rowptr finalize. Each block rebuilds the 49-entry chunk-offset
// LUT in shared memory (cheap) -- no grid sync anywhere.
__global__ void __launch_bounds__(256)
k_fill(const int* __restrict__ src, const int* __restrict__ dst,
       const float* __restrict__ e_in,
       const float* __restrict__ rs, const float* __restrict__ sigma)
{
    __shared__ int lut[N_CHUNKS];                 // exclusive prefix of chunk sums
    if (threadIdx.x == 0) {
        int run = 0;
        for (int c = 0; c < N_CHUNKS; c++) { lut[c] = run; run += g_bsum[c]; }
    }
    __syncthreads();

    int stride = gridDim.x * blockDim.x;
    int t0 = blockIdx.x * blockDim.x + threadIdx.x;

    // finalize rowptr for the aggregate kernel
    for (int i = t0; i < N_NODES; i += stride)
        g_rowptr[i + 1] = g_rowloc[i + 1] + lut[i >> 10];

    // scatter edges into CSR order; envelope f stored as duplicated half2
    float rsv = rs[0], sg = sigma[0];
    for (int e = t0; e < N_EDGES; e += stride) {
        int n = dst[e];
        int base = (n == 0) ? 0 : (g_rowloc[n] + lut[(n - 1) >> 10]);
        int p = base + g_slot[e];
        float r   = e_in[e];
        float d   = r - rsv;
        float gau = expf(-(d * d) / (sg * sg));
        float cut = (r < RC) ? 0.5f * cosf(0.62831853071795864769f * r) : 0.0f; // pi/RC
        __half2 fh = __float2half2_rn(gau * cut);
        g_csr[p] = make_int2(src[e], (int)*reinterpret_cast<unsigned*>(&fh));
    }
}

// one warp per node: xh[n] = fp16( v[n] + sum_{edges->n} f * curh[src] )
// Half-warp per edge (16 lanes x uint4 = 256B row), 2 edges per warp-iter.
// fp16 HFMA2 accumulation, flushed to fp32 every 8 edges; cross-half
// shfl_xor(16) reduction at the end. Meta staged in warp-private SMEM.
__global__ void __launch_bounds__(256)
k_aggregate(const float* __restrict__ v)
{
    __shared__ int2 s_meta[8][32];
    int gtid = blockIdx.x * blockDim.x + threadIdx.x;
    int node = gtid >> 5;
    int lane = gtid & 31;
    int w    = threadIdx.x >> 5;
    if (node >= N_NODES) return;

    int half_id = lane >> 4;      // which edge of the pair
    int sub     = lane & 15;      // 8-dim group within row (uint4 index)

    int p0 = __ldg(&g_rowptr[node]);
    int p1 = __ldg(&g_rowptr[node + 1]);

    const uint4* in = reinterpret_cast<const uint4*>(g_curh);  // 16 uint4 per row

    float accf[8];
#pragma unroll
    for (int i = 0; i < 8; i++) accf[i] = 0.f;

    const __half2 hzero = __float2half2_rn(0.f);

    for (int base = p0; base < p1; base += 32) {
        int idx = base + lane;
        if (idx < p1) s_meta[w][lane] = __ldg(&g_csr[idx]);
        __syncwarp();
        int cnt = min(32, p1 - base);
        for (int j2 = 0; j2 < cnt; j2 += 8) {
            __half2 h0 = hzero, h1 = hzero, h2 = hzero, h3 = hzero;
#pragma unroll
            for (int u = 0; u < 4; u++) {
                int j = j2 + u * 2 + half_id;
                bool act = j < cnt;
                int2 m = s_meta[w][act ? j : 0];
                unsigned fb = act ? (unsigned)m.y : 0u;
                __half2 fh = *reinterpret_cast<__half2*>(&fb);
                uint4 r = __ldg(&in[(size_t)m.x * 16 + sub]);
                h0 = __hfma2(fh, *reinterpret_cast<__half2*>(&r.x), h0);
                h1 = __hfma2(fh, *reinterpret_cast<__half2*>(&r.y), h1);
                h2 = __hfma2(fh, *reinterpret_cast<__half2*>(&r.z), h2);
                h3 = __hfma2(fh, *reinterpret_cast<__half2*>(&r.w), h3);
            }
            float2 f0 = __half22float2(h0);
            float2 f1 = __half22float2(h1);
            float2 f2 = __half22float2(h2);
            float2 f3 = __half22float2(h3);
            accf[0] += f0.x; accf[1] += f0.y;
            accf[2] += f1.x; accf[3] += f1.y;
            accf[4] += f2.x; accf[5] += f2.y;
            accf[6] += f3.x; accf[7] += f3.y;
        }
        __syncwarp();
    }

    // merge the two half-warp partial sums (same dims, different edges)
#pragma unroll
    for (int i = 0; i < 8; i++)
        accf[i] += __shfl_xor_sync(0xffffffffu, accf[i], 16);

    if (half_id == 0) {
        const float4* vr = reinterpret_cast<const float4*>(v + (size_t)node * DIM + sub * 8);
        float4 v0 = vr[0];
        float4 v1 = vr[1];
        accf[0] += v0.x; accf[1] += v0.y; accf[2] += v0.z; accf[3] += v0.w;
        accf[4] += v1.x; accf[5] += v1.y; accf[6] += v1.z; accf[7] += v1.w;
        __half2 o0 = __floats2half2_rn(accf[0], accf[1]);
        __half2 o1 = __floats2half2_rn(accf[2], accf[3]);
        __half2 o2 = __floats2half2_rn(accf[4], accf[5]);
        __half2 o3 = __floats2half2_rn(accf[6], accf[7]);
        uint4 raw;
        raw.x = *reinterpret_cast<unsigned*>(&o0);
        raw.y = *reinterpret_cast<unsigned*>(&o1);
        raw.z = *reinterpret_cast<unsigned*>(&o2);
        raw.w = *reinterpret_cast<unsigned*>(&o3);
        reinterpret_cast<uint4*>(g_xh)[(size_t)node * 16 + sub] = raw;
    }
}

// out = relu(x @ A^T + b) on tensor cores: mma.sync m16n8k16 f16 -> f32.
// Block 256 thr = 8 warps; tile 64 rows x 128 cols; warp = 16 rows x 64 cols.
#define LIN_ROWS 64
#define PADK     136   // smem stride in halfs: word stride 68 -> conflict-free frags
__global__ void __launch_bounds__(256)
k_linear(const float* __restrict__ A, const float* __restrict__ b,
         float* __restrict__ dout, int last)
{
    extern __shared__ __half smem[];
    __half* As = smem;                       // [c][k] stride PADK  (B operand)
    __half* xs = smem + DIM * PADK;          // [m][k] stride PADK  (A operand)

    int tid  = threadIdx.x;
    int wid  = tid >> 5;
    int lane = tid & 31;
    int g    = lane >> 2;                    // 0..7
    int tg   = lane & 3;                     // 0..3
    int wm   = wid & 3;                      // m-quadrant (16 rows)
    int wn   = wid >> 2;                     // n-half (64 cols)

    // As[c][k] = fp16(A[c*128 + k])  (A_w native layout; no transpose needed)
    for (int idx = tid; idx < DIM * DIM; idx += 256) {
        int c = idx >> 7, k = idx & 127;
        As[c * PADK + k] = __float2half_rn(A[idx]);
    }
    // xs rows (zero-pad past N_NODES)
    int row0 = blockIdx.x * LIN_ROWS;
    unsigned* xs32 = reinterpret_cast<unsigned*>(xs);
    const unsigned* xh32 = reinterpret_cast<const unsigned*>(g_xh);
    for (int idx = tid; idx < LIN_ROWS * 64; idx += 256) {   // u32 units (2 halfs)
        int r = idx >> 6, kk = idx & 63;
        unsigned val = (row0 + r < N_NODES) ? xh32[(size_t)(row0 + r) * 64 + kk] : 0u;
        xs32[r * (PADK / 2) + kk] = val;
    }
    __syncthreads();

    float d[8][4];
#pragma unroll
    for (int nt = 0; nt < 8; nt++)
#pragma unroll
        for (int j = 0; j < 4; j++) d[nt][j] = 0.f;

    const unsigned* xsu = reinterpret_cast<const unsigned*>(xs);
    const unsigned* asu = reinterpret_cast<const unsigned*>(As);
    int m0 = wm * 16;
    int n0 = wn * 64;

#pragma unroll
    for (int kt = 0; kt < 8; kt++) {
        int k0 = kt * 16;
        // A fragment (x tile): rows {m0+g, m0+g+8}, k pairs {2tg, 2tg+8}
        unsigned a0 = xsu[(m0 + g)     * 68 + (k0 >> 1) + tg];
        unsigned a1 = xsu[(m0 + g + 8) * 68 + (k0 >> 1) + tg];
        unsigned a2 = xsu[(m0 + g)     * 68 + (k0 >> 1) + tg + 4];
        unsigned a3 = xsu[(m0 + g + 8) * 68 + (k0 >> 1) + tg + 4];
#pragma unroll
        for (int nt = 0; nt < 8; nt++) {
            int n = n0 + nt * 8 + g;
            unsigned b0 = asu[n * 68 + (k0 >> 1) + tg];
            unsigned b1 = asu[n * 68 + (k0 >> 1) + tg + 4];
            asm volatile(
                "mma.sync.aligned.m16n8k16.row.col.f32.f16.f16.f32 "
                "{%0,%1,%2,%3}, {%4,%5,%6,%7}, {%8,%9}, {%0,%1,%2,%3};"
                : "+f"(d[nt][0]), "+f"(d[nt][1]), "+f"(d[nt][2]), "+f"(d[nt][3])
                : "r"(a0), "r"(a1), "r"(a2), "r"(a3), "r"(b0), "r"(b1));
        }
    }

    // epilogue: bias + relu; thread owns cols {n0+nt*8+2tg,+1}, rows {m0+g, m0+g+8}
#pragma unroll
    for (int nt = 0; nt < 8; nt++) {
        int col = n0 + nt * 8 + tg * 2;
        float2 bb = *reinterpret_cast<const float2*>(b + col);
        float o0 = fmaxf(d[nt][0] + bb.x, 0.f);
        float o1 = fmaxf(d[nt][1] + bb.y, 0.f);
        float o2 = fmaxf(d[nt][2] + bb.x, 0.f);
        float o3 = fmaxf(d[nt][3] + bb.y, 0.f);
        int r0 = row0 + m0 + g;
        int r1 = r0 + 8;
        if (last) {
            if (r0 < N_NODES)
                *reinterpret_cast<float2*>(dout + (size_t)r0 * DIM + col) = make_float2(o0, o1);
            if (r1 < N_NODES)
                *reinterpret_cast<float2*>(dout + (size_t)r1 * DIM + col) = make_float2(o2, o3);
        } else {
            unsigned* ch = reinterpret_cast<unsigned*>(g_curh);
            if (r0 < N_NODES) {
                __half2 h = __floats2half2_rn(o0, o1);
                ch[(size_t)r0 * 64 + (col >> 1)] = *reinterpret_cast<unsigned*>(&h);
            }
            if (r1 < N_NODES) {
                __half2 h = __floats2half2_rn(o2, o3);
                ch[(size_t)r1 * 64 + (col >> 1)] = *reinterpret_cast<unsigned*>(&h);
            }
        }
    }
}

// ---------------------------------------------------------------------------
extern "C" void kernel_launch(void* const* d_in, const int* in_sizes, int n_in,
                              void* d_out, int out_size)
{
    const float* v     = (const float*)d_in[0];
    const float* e     = (const float*)d_in[1];
    const int*   src   = (const int*)d_in[2];
    const int*   dst   = (const int*)d_in[3];
    const float* A_w   = (const float*)d_in[4];
    const float* A_b   = (const float*)d_in[5];
    const float* rs    = (const float*)d_in[6];
    const float* sigma = (const float*)d_in[7];
    float* out = (float*)d_out;

    (void)in_sizes; (void)n_in; (void)out_size;

    const int SMEM_LIN = (DIM + LIN_ROWS) * PADK * (int)sizeof(__half); // ~51KB
    (void)cudaFuncSetAttribute(k_linear, cudaFuncAttributeMaxDynamicSharedMemorySize, SMEM_LIN);

    // zero the histogram with a memset node (graph-capturable, not an alloc)
    void* counts_ptr = nullptr;
    (void)cudaGetSymbolAddress(&counts_ptr, g_counts);
    (void)cudaMemsetAsync(counts_ptr, 0, N_NODES * sizeof(int));

    int gE = (N_EDGES + 255) / 256;

    k_hist <<<gE, 256>>>(dst, v);
    k_scan1<<<N_CHUNKS, SCAN_BLK>>>();
    k_fill <<<2048, 256>>>(src, dst, e, rs, sigma);

    int aggBlocks = (N_NODES * 32 + 255) / 256;           // warp per node
    int linBlocks = (N_NODES + LIN_ROWS - 1) / LIN_ROWS;  // 782

    for (int d = 0; d < DEPTH; d++) {
        k_aggregate<<<aggBlocks, 256>>>(v);
        k_linear<<<linBlocks, 256, SMEM_LIN>>>(A_w, A_b, out, d == DEPTH - 1 ? 1 : 0);
    }
}